// round 3
// baseline (speedup 1.0000x reference)
#include <cuda_runtime.h>
#include <cstdint>

#define B_T    16000      // B*T rows
#define D_IN   320
#define E_DIM  16
#define K_CB   8192
#define KSPLIT 8
#define KSEG   (K_CB / KSPLIT)        // 1024 candidates per segment
#define CHUNK  512                    // candidates staged in smem per pass
#define NCHUNK (KSEG / CHUNK)         // 2
#define ROWS_PB 64                    // rows per block (32 lanes * 2 rows/thread)
#define NBLK_ROWS (B_T / ROWS_PB)     // 250
#define T2     256

// ---- scratch (device globals are the sanctioned no-alloc path) ----
__device__ float g_V[B_T * E_DIM];
__device__ float g_pv[KSPLIT * B_T];
__device__ int   g_pi[KSPLIT * B_T];

// ============================================================================
// Kernel 1: V[row][e] = sum_d H[row][d] * P[d][e]   (plain scalar fmaf)
// ============================================================================
__global__ __launch_bounds__(256) void proj_kernel(const float* __restrict__ H,
                                                   const float* __restrict__ P) {
    __shared__ float Ps[D_IN * E_DIM];    // 20 KB
    for (int i = threadIdx.x; i < D_IN * E_DIM; i += 256) Ps[i] = P[i];
    __syncthreads();

    int row = blockIdx.x * 256 + threadIdx.x;
    if (row >= B_T) return;

    float acc[E_DIM];
#pragma unroll
    for (int e = 0; e < E_DIM; ++e) acc[e] = 0.0f;

    const float4* h4 = (const float4*)(H + (size_t)row * D_IN);
    for (int d4 = 0; d4 < D_IN / 4; ++d4) {
        float4 h = h4[d4];
        const float* p0 = &Ps[(d4 * 4 + 0) * E_DIM];
        const float* p1 = &Ps[(d4 * 4 + 1) * E_DIM];
        const float* p2 = &Ps[(d4 * 4 + 2) * E_DIM];
        const float* p3 = &Ps[(d4 * 4 + 3) * E_DIM];
#pragma unroll
        for (int e = 0; e < E_DIM; ++e) {
            float a = acc[e];
            a = fmaf(h.x, p0[e], a);
            a = fmaf(h.y, p1[e], a);
            a = fmaf(h.z, p2[e], a);
            a = fmaf(h.w, p3[e], a);
            acc[e] = a;
        }
    }
    float* vout = g_V + (size_t)row * E_DIM;
#pragma unroll
    for (int e = 0; e < E_DIM; ++e) vout[e] = acc[e];
}

// ============================================================================
// Kernel 2: fused scores + argmax over one K segment.
// grid = (250 row-groups, 8 ksegs). 8 warps; lanes = 32 rows, 2 rows/thread.
// CB chunk (512 cands, 32 KB) in smem; all lanes of a warp read the SAME
// candidate row -> pure LDS broadcast.
// ============================================================================
__device__ __forceinline__ float dot16s(float4 a, float4 b, float4 c, float4 d,
                                        const float* __restrict__ v) {
    float t0 = a.x * v[0],  t1 = a.y * v[1],  t2 = a.z * v[2],  t3 = a.w * v[3];
    t0 = fmaf(b.x, v[4],  t0); t1 = fmaf(b.y, v[5],  t1);
    t2 = fmaf(b.z, v[6],  t2); t3 = fmaf(b.w, v[7],  t3);
    t0 = fmaf(c.x, v[8],  t0); t1 = fmaf(c.y, v[9],  t1);
    t2 = fmaf(c.z, v[10], t2); t3 = fmaf(c.w, v[11], t3);
    t0 = fmaf(d.x, v[12], t0); t1 = fmaf(d.y, v[13], t1);
    t2 = fmaf(d.z, v[14], t2); t3 = fmaf(d.w, v[15], t3);
    return (t0 + t1) + (t2 + t3);
}

__global__ __launch_bounds__(T2) void score_kernel(const float* __restrict__ CB) {
    __shared__ float4 cb_s[CHUNK * 4];          // 32 KB
    __shared__ float  red_v[8][ROWS_PB];        // 2 KB
    __shared__ int    red_i[8][ROWS_PB];        // 2 KB

    const int tid  = threadIdx.x;
    const int lane = tid & 31;
    const int warp = tid >> 5;
    const int row_base = blockIdx.x * ROWS_PB;
    const int kseg = blockIdx.y;

    // this thread's two row vectors (16 floats each)
    float v0[E_DIM], v1[E_DIM];
    {
        const float4* V0 = (const float4*)(g_V + (size_t)(row_base + lane) * E_DIM);
        const float4* V1 = (const float4*)(g_V + (size_t)(row_base + 32 + lane) * E_DIM);
#pragma unroll
        for (int j = 0; j < 4; ++j) {
            float4 a = V0[j];
            v0[4 * j] = a.x; v0[4 * j + 1] = a.y; v0[4 * j + 2] = a.z; v0[4 * j + 3] = a.w;
            float4 b = V1[j];
            v1[4 * j] = b.x; v1[4 * j + 1] = b.y; v1[4 * j + 2] = b.z; v1[4 * j + 3] = b.w;
        }
    }

    float best0 = __int_as_float(0xff800000);   // -inf
    float best1 = __int_as_float(0xff800000);
    int bi0 = 0, bi1 = 0;

    const float4* cbg = (const float4*)CB;
    for (int c = 0; c < NCHUNK; ++c) {
        __syncthreads();
        {   // stage chunk: 512 cands * 64 B = 2048 float4
            const float4* src = cbg + ((size_t)kseg * KSEG + (size_t)c * CHUNK) * 4;
#pragma unroll
            for (int i = 0; i < (CHUNK * 4) / T2; ++i)
                cb_s[tid + i * T2] = src[tid + i * T2];
        }
        __syncthreads();

        const int jbase = warp * (CHUNK / 8);               // 64-cand stripe / warp
        const int kbase = kseg * KSEG + c * CHUNK + jbase;
#pragma unroll 4
        for (int j = 0; j < CHUNK / 8; ++j) {
            const float4* q = &cb_s[(size_t)(jbase + j) * 4];
            float4 a = q[0], b = q[1], cc = q[2], d = q[3];
            float s0 = dot16s(a, b, cc, d, v0);
            float s1 = dot16s(a, b, cc, d, v1);
            int k = kbase + j;
            if (s0 > best0) { best0 = s0; bi0 = k; }        // strict > == first-max
            if (s1 > best1) { best1 = s1; bi1 = k; }
        }
    }

    // cross-warp reduce (warps hold disjoint k-stripes of the same 64 rows)
    red_v[warp][lane]      = best0;  red_i[warp][lane]      = bi0;
    red_v[warp][32 + lane] = best1;  red_i[warp][32 + lane] = bi1;
    __syncthreads();
    if (tid < ROWS_PB) {
        float bv = red_v[0][tid]; int bi = red_i[0][tid];
#pragma unroll
        for (int w = 1; w < 8; ++w) {
            float v = red_v[w][tid]; int i = red_i[w][tid];
            if (v > bv || (v == bv && i < bi)) { bv = v; bi = i; }
        }
        g_pv[(size_t)kseg * B_T + row_base + tid] = bv;
        g_pi[(size_t)kseg * B_T + row_base + tid] = bi;
    }
}

// ============================================================================
// Kernel 3: combine KSPLIT partials per row (value, then lower index on ties).
// Output written as FLOAT VALUES of the label: an int32 bit-pattern label in a
// float32 output buffer reads as a denormal ~1e-41 -> the exact rel_err=1.0
// signature observed in rounds 1-2.
// ============================================================================
__global__ __launch_bounds__(256) void combine_kernel(float* __restrict__ out) {
    int row = blockIdx.x * 256 + threadIdx.x;
    if (row >= B_T) return;
    float bv = g_pv[row];
    int   bi = g_pi[row];
#pragma unroll
    for (int s = 1; s < KSPLIT; ++s) {
        float v = g_pv[(size_t)s * B_T + row];
        int   i = g_pi[(size_t)s * B_T + row];
        if (v > bv || (v == bv && i < bi)) { bv = v; bi = i; }
    }
    out[row] = (float)bi;     // label as float VALUE
}

// ============================================================================
extern "C" void kernel_launch(void* const* d_in, const int* in_sizes, int n_in,
                              void* d_out, int out_size) {
    // Input dispatch by element count (ordering-proof):
    //   H  = 16000*320 = 5,120,000 ; P = 320*16 = 5,120 ; CB = 8192*16 = 131,072
    const float* H  = nullptr;
    const float* P  = nullptr;
    const float* CB = nullptr;
    for (int i = 0; i < n_in; ++i) {
        if      (in_sizes[i] == B_T * D_IN)   H  = (const float*)d_in[i];
        else if (in_sizes[i] == D_IN * E_DIM) P  = (const float*)d_in[i];
        else if (in_sizes[i] == K_CB * E_DIM) CB = (const float*)d_in[i];
    }
    if (!H)  H  = (const float*)d_in[0];
    if (!P)  P  = (const float*)d_in[1];
    if (!CB) CB = (const float*)d_in[2];

    float* out = (float*)d_out;

    proj_kernel<<<(B_T + 255) / 256, 256>>>(H, P);
    score_kernel<<<dim3(NBLK_ROWS, KSPLIT), T2>>>(CB);
    combine_kernel<<<(B_T + 255) / 256, 256>>>(out);
}